// round 14
// baseline (speedup 1.0000x reference)
#include <cuda_runtime.h>
#include <cuda_bf16.h>
#include <cstdint>

#define N_REL   32
#define N_BASES 30
#define IN_F    64
#define OUT_F   64
#define MAX_NODES 100000
#define MAX_EDGES 1000000
#define TE      128   // rows per tile

// ---------------- device scratch (static, allocation-free) ----------------
__device__ __nv_bfloat16  g_Wbf[N_REL * OUT_F * IN_F];   // bf16 W^T per relation, ROW-PERMUTED
__device__ __nv_bfloat16  g_SWhi[OUT_F * IN_F];          // self_weight^T hi, ROW-PERMUTED
__device__ __nv_bfloat16  g_SWlo[OUT_F * IN_F];          // self_weight^T lo, ROW-PERMUTED
__device__ __nv_bfloat16  g_nfb[MAX_NODES * IN_F];       // bf16 node features (128B rows)
__device__ float g_deg[MAX_NODES];
__device__ float g_inv[MAX_NODES];
__device__ int   g_hist[N_REL];
__device__ int   g_commit[N_REL];
__device__ int2  g_pair[MAX_EDGES];                      // (sender, receiver) sorted by relation

// Permutation: logical output col o lives at physical B-row p(o).
// o = 16*tg + 2*j + b  ->  p = 8*j + 2*tg + b
// => thread tg's fragment cols are logical [16tg, 16tg+16) CONSECUTIVE.
__host__ __device__ __forceinline__ int permcol(int o) {
    return 8 * ((o >> 1) & 7) + 2 * (o >> 4) + (o & 1);
}

// ---------------- helpers ----------------
__device__ __forceinline__ uint32_t smem_u32(const void* p) {
    uint32_t a;
    asm("{ .reg .u64 t; cvta.to.shared.u64 t, %1; cvt.u32.u64 %0, t; }" : "=r"(a) : "l"(p));
    return a;
}
__device__ __forceinline__ uint32_t bf2pack(float lo, float hi) {
    uint32_t r;
    asm("cvt.rn.bf16x2.f32 %0, %1, %2;" : "=r"(r) : "f"(hi), "f"(lo));
    return r;
}
__device__ __forceinline__ void sts128(uint32_t addr, uint32_t a, uint32_t b, uint32_t c, uint32_t d) {
    asm volatile("st.shared.v4.b32 [%0], {%1, %2, %3, %4};" :: "r"(addr), "r"(a), "r"(b), "r"(c), "r"(d) : "memory");
}
__device__ __forceinline__ void red2f(float* p, float a, float b) {
    asm volatile("red.global.add.v2.f32 [%0], {%1, %2};" :: "l"(p), "f"(a), "f"(b) : "memory");
}
__device__ __forceinline__ void ldm_x4(uint32_t& r0, uint32_t& r1, uint32_t& r2, uint32_t& r3,
                                       uint32_t addr) {
    asm volatile("ldmatrix.sync.aligned.m8n8.x4.shared.b16 {%0, %1, %2, %3}, [%4];"
                 : "=r"(r0), "=r"(r1), "=r"(r2), "=r"(r3) : "r"(addr));
}
__device__ __forceinline__ void mma_bf16(float* d, uint32_t a0, uint32_t a1, uint32_t a2,
                                         uint32_t a3, uint32_t b0, uint32_t b1) {
    asm volatile("mma.sync.aligned.m16n8k16.row.col.f32.bf16.bf16.f32 "
                 "{%0, %1, %2, %3}, {%4, %5, %6, %7}, {%8, %9}, {%0, %1, %2, %3};"
                 : "+f"(d[0]), "+f"(d[1]), "+f"(d[2]), "+f"(d[3])
                 : "r"(a0), "r"(a1), "r"(a2), "r"(a3), "r"(b0), "r"(b1));
}

#define SW128(o) ((o) ^ (((o) >> 3) & 0x70))
#define ZERO_BLOCKS ((MAX_NODES + 255) / 256)
#define NFB_BLOCKS  ((MAX_NODES * 8 + 255) / 256)   // 8 floats -> 8 bf16 per thread

// One MMA pass over a 128x64 @ 64x64 tile pair; accumulates into acc.
__device__ __forceinline__ void mma_tile_pass(uint32_t sA, uint32_t sB, int w, int lane,
                                              float (&acc)[2][8][4]) {
    #pragma unroll
    for (int k = 0; k < 4; k++) {
        uint32_t a[2][4];
        #pragma unroll
        for (int mt = 0; mt < 2; mt++) {
            uint32_t row = (uint32_t)(w * 32 + mt * 16 + (((lane >> 3) & 1) << 3) + (lane & 7));
            uint32_t kb  = (uint32_t)(32 * k + (((lane >> 4) & 1) << 4));
            ldm_x4(a[mt][0], a[mt][1], a[mt][2], a[mt][3], sA + SW128(row * 128u + kb));
        }
        uint32_t bf[8][2];
        #pragma unroll
        for (int jp = 0; jp < 4; jp++) {
            uint32_t jl   = (uint32_t)((lane >> 4) & 1);
            uint32_t half = (uint32_t)((lane >> 3) & 1);
            uint32_t rowb = (uint32_t)(8 * (2 * jp + jl) + (lane & 7));
            uint32_t kb   = (uint32_t)(32 * k + 16 * half);
            ldm_x4(bf[2 * jp][0], bf[2 * jp][1], bf[2 * jp + 1][0], bf[2 * jp + 1][1],
                   sB + SW128(rowb * 128u + kb));
        }
        #pragma unroll
        for (int mt = 0; mt < 2; mt++)
            #pragma unroll
            for (int j = 0; j < 8; j++)
                mma_bf16(acc[mt][j], a[mt][0], a[mt][1], a[mt][2], a[mt][3],
                         bf[j][0], bf[j][1]);
    }
}

// ---------------- setup: zero deg/hist + nf->bf16 + permuted W_r + permuted SW hi/lo ----------------
__global__ void setup_k(const float* __restrict__ basis, const float* __restrict__ coeff,
                        const float* __restrict__ sw, const float* __restrict__ nf, int N) {
    int b = blockIdx.x;
    if (b < ZERO_BLOCKS) {
        int i = b * 256 + threadIdx.x;
        if (i < N) g_deg[i] = 0.f;
        if (b == 0 && threadIdx.x < N_REL) {
            g_hist[threadIdx.x] = 0;
            g_commit[threadIdx.x] = 0;
        }
        return;
    }
    if (b < ZERO_BLOCKS + NFB_BLOCKS) {
        int i = (b - ZERO_BLOCKS) * 256 + threadIdx.x;  // 8-float group index
        if (i < N * 8) {
            const float4* src = (const float4*)nf + 2 * (size_t)i;
            float4 f0 = src[0];
            float4 f1 = src[1];
            ((uint4*)g_nfb)[i] = make_uint4(bf2pack(f0.x, f0.y), bf2pack(f0.z, f0.w),
                                            bf2pack(f1.x, f1.y), bf2pack(f1.z, f1.w));
        }
        return;
    }
    if (b == ZERO_BLOCKS + NFB_BLOCKS + N_REL) {
        // split self_weight^T into bf16 hi + lo, with permuted row order
        for (int idx = threadIdx.x; idx < IN_F * OUT_F; idx += blockDim.x) {
            int i = idx / OUT_F, o = idx % OUT_F;
            float x = sw[idx];
            __nv_bfloat16 h = __float2bfloat16(x);
            float lo = x - __bfloat162float(h);
            int p = permcol(o);
            g_SWhi[p * IN_F + i] = h;
            g_SWlo[p * IN_F + i] = __float2bfloat16(lo);
        }
        return;
    }
    int r = b - ZERO_BLOCKS - NFB_BLOCKS;  // 0..N_REL-1
    __shared__ float c[N_BASES];
    if (threadIdx.x < N_BASES) c[threadIdx.x] = coeff[r * N_BASES + threadIdx.x];
    __syncthreads();
    for (int idx = threadIdx.x; idx < IN_F * OUT_F; idx += blockDim.x) {
        float acc = 0.f;
        #pragma unroll
        for (int bb = 0; bb < N_BASES; bb++)
            acc += c[bb] * basis[bb * IN_F * OUT_F + idx];
        int i = idx / OUT_F, o = idx % OUT_F;
        g_Wbf[r * IN_F * OUT_F + permcol(o) * IN_F + i] = __float2bfloat16(acc);  // W^T permuted
    }
}

__global__ void hist_deg_k(const int* __restrict__ rel, const int* __restrict__ recv, int E) {
    __shared__ int h[N_REL];
    if (threadIdx.x < N_REL) h[threadIdx.x] = 0;
    __syncthreads();
    for (int e = blockIdx.x * blockDim.x + threadIdx.x; e < E; e += gridDim.x * blockDim.x) {
        atomicAdd(&h[rel[e]], 1);
        atomicAdd(&g_deg[recv[e]], 1.f);
    }
    __syncthreads();
    if (threadIdx.x < N_REL) atomicAdd(&g_hist[threadIdx.x], h[threadIdx.x]);
}

// counting-sort pass: writes (sender, receiver) int2 per edge, relation-sorted
__global__ void scatter_k(const int* __restrict__ rel,
                          const int* __restrict__ senders,
                          const int* __restrict__ receivers, int E) {
    __shared__ int cnt[N_REL];
    __shared__ int basee[N_REL];
    __shared__ int off_s[N_REL];
    int tid = threadIdx.x;
    if (tid < 32) {
        int h = (tid < N_REL) ? g_hist[tid] : 0;
        int x = h;
        #pragma unroll
        for (int d = 1; d < 32; d <<= 1) {
            int y = __shfl_up_sync(0xffffffffu, x, d);
            if (tid >= d) x += y;
        }
        if (tid < N_REL) off_s[tid] = x - h;  // exclusive prefix
    }
    __syncthreads();
    if (tid < N_REL) cnt[tid] = 0;
    __syncthreads();

    int chunk = (E + gridDim.x - 1) / gridDim.x;
    int s = blockIdx.x * chunk;
    int e_end = min(E, s + chunk);
    for (int i = s + tid; i < e_end; i += blockDim.x)
        atomicAdd(&cnt[rel[i]], 1);
    __syncthreads();
    if (tid < N_REL)
        basee[tid] = off_s[tid] + atomicAdd(&g_commit[tid], cnt[tid]);
    __syncthreads();
    if (tid < N_REL) cnt[tid] = 0;
    __syncthreads();
    for (int i = s + tid; i < e_end; i += blockDim.x) {
        int r = rel[i];
        int p = atomicAdd(&cnt[r], 1);
        g_pair[basee[r] + p] = make_int2(senders[i], receivers[i]);
    }
}

// ---------------- self term (bf16-split HMMA), runs BEFORE edge ----------------
// out = X@SW + bias ; also produces g_inv = 1/max(deg,1) for the edge kernel.
__global__ void __launch_bounds__(128) self_hmma_k(const float* __restrict__ nf,
                                                   const float* __restrict__ bias,
                                                   float* __restrict__ out, int N) {
    __shared__ __align__(128) uint8_t sm[TE * 128 * 2 + OUT_F * 128 * 2];  // Ah,Al,Bh,Bl = 48KB
    int tid  = threadIdx.x;
    int w    = tid >> 5;
    int lane = tid & 31;
    int base = blockIdx.x * TE;
    int nR   = min(TE, N - base);

    uint32_t sAh = smem_u32(sm);
    uint32_t sAl = sAh + TE * 128;
    uint32_t sBh = sAl + TE * 128;
    uint32_t sBl = sBh + OUT_F * 128;

    // fused inv_deg for this block's rows (consumed by the edge kernel)
    if (tid < nR)
        g_inv[base + tid] = 1.f / fmaxf(g_deg[base + tid], 1.f);

    // stage B hi/lo (already permuted in setup)
    {
        const uint4* bh = (const uint4*)g_SWhi;
        const uint4* bl = (const uint4*)g_SWlo;
        #pragma unroll
        for (int i = tid; i < 512; i += 128) {
            uint32_t off = SW128((uint32_t)i * 16u);
            uint4 vh = bh[i];
            uint4 vl = bl[i];
            sts128(sBh + off, vh.x, vh.y, vh.z, vh.w);
            sts128(sBl + off, vl.x, vl.y, vl.z, vl.w);
        }
    }

    // load + split A row `tid`
    {
        uint32_t rowbase = (uint32_t)tid * 128u;
        if (tid < nR) {
            const float4* src = (const float4*)(nf + (size_t)(base + tid) * IN_F);
            #pragma unroll
            for (int c = 0; c < 4; c++) {
                float4 f0 = src[4 * c + 0];
                float4 f1 = src[4 * c + 1];
                float4 f2 = src[4 * c + 2];
                float4 f3 = src[4 * c + 3];
                float tmp[16] = {f0.x,f0.y,f0.z,f0.w, f1.x,f1.y,f1.z,f1.w,
                                 f2.x,f2.y,f2.z,f2.w, f3.x,f3.y,f3.z,f3.w};
                float hf[16], lf[16];
                #pragma unroll
                for (int q = 0; q < 16; q++) {
                    __nv_bfloat16 h = __float2bfloat16(tmp[q]);
                    hf[q] = __bfloat162float(h);
                    lf[q] = tmp[q] - hf[q];
                }
                uint32_t offA = rowbase + (uint32_t)c * 32u;
                sts128(sAh + SW128(offA),
                       bf2pack(hf[0], hf[1]), bf2pack(hf[2], hf[3]),
                       bf2pack(hf[4], hf[5]), bf2pack(hf[6], hf[7]));
                sts128(sAh + SW128(offA + 16u),
                       bf2pack(hf[8], hf[9]), bf2pack(hf[10], hf[11]),
                       bf2pack(hf[12], hf[13]), bf2pack(hf[14], hf[15]));
                sts128(sAl + SW128(offA),
                       bf2pack(lf[0], lf[1]), bf2pack(lf[2], lf[3]),
                       bf2pack(lf[4], lf[5]), bf2pack(lf[6], lf[7]));
                sts128(sAl + SW128(offA + 16u),
                       bf2pack(lf[8], lf[9]), bf2pack(lf[10], lf[11]),
                       bf2pack(lf[12], lf[13]), bf2pack(lf[14], lf[15]));
            }
        } else {
            #pragma unroll
            for (int c = 0; c < 8; c++) {
                uint32_t off = rowbase + (uint32_t)c * 16u;
                sts128(sAh + SW128(off), 0u, 0u, 0u, 0u);
                sts128(sAl + SW128(off), 0u, 0u, 0u, 0u);
            }
        }
    }
    __syncthreads();

    float acc[2][8][4];
    #pragma unroll
    for (int mt = 0; mt < 2; mt++)
        #pragma unroll
        for (int j = 0; j < 8; j++)
            #pragma unroll
            for (int q = 0; q < 4; q++) acc[mt][j][q] = 0.f;

    mma_tile_pass(sAh, sBh, w, lane, acc);
    mma_tile_pass(sAh, sBl, w, lane, acc);
    mma_tile_pass(sAl, sBh, w, lane, acc);

    // epilogue: thread owns logical cols [16tg, 16tg+16) -> float4 stores of acc+bias
    int g  = lane >> 2;
    int tg = lane & 3;
    float4 bv[4];
    #pragma unroll
    for (int q = 0; q < 4; q++) bv[q] = *(const float4*)&bias[16 * tg + 4 * q];
    #pragma unroll
    for (int mt = 0; mt < 2; mt++) {
        int r1 = base + w * 32 + mt * 16 + g;
        int r2 = r1 + 8;
        #pragma unroll
        for (int q = 0; q < 4; q++) {
            if (r1 < N)
                *(float4*)(out + (size_t)r1 * OUT_F + 16 * tg + 4 * q) = make_float4(
                    acc[mt][2 * q][0] + bv[q].x, acc[mt][2 * q][1] + bv[q].y,
                    acc[mt][2 * q + 1][0] + bv[q].z, acc[mt][2 * q + 1][1] + bv[q].w);
            if (r2 < N)
                *(float4*)(out + (size_t)r2 * OUT_F + 16 * tg + 4 * q) = make_float4(
                    acc[mt][2 * q][2] + bv[q].x, acc[mt][2 * q][3] + bv[q].y,
                    acc[mt][2 * q + 1][2] + bv[q].z, acc[mt][2 * q + 1][3] + bv[q].w);
        }
    }
}

// ---------------- edge messages: coalesced bf16 gather -> HMMA -> red.v2.f32 into out ----------------
__global__ void __launch_bounds__(128, 4)
edge_mma_k(float* __restrict__ out) {
    __shared__ __align__(128) uint8_t sAB[TE * 128 + OUT_F * 128];  // A:16KB, B:8KB
    __shared__ int   s_rc[TE];
    __shared__ float s_inv[TE];
    __shared__ int   s_h[N_REL];
    __shared__ int   s_ti[N_REL];
    __shared__ int   s_off[N_REL];

    int tid  = threadIdx.x;
    int w    = tid >> 5;
    int lane = tid & 31;
    int b    = blockIdx.x;

    // local 32-wide scan of g_hist (tile->relation mapping)
    if (tid < 32) {
        int h = (tid < N_REL) ? g_hist[tid] : 0;
        int t = (h + TE - 1) / TE;
        int xh = h, xt = t;
        #pragma unroll
        for (int d = 1; d < 32; d <<= 1) {
            int yh = __shfl_up_sync(0xffffffffu, xh, d);
            int yt = __shfl_up_sync(0xffffffffu, xt, d);
            if (tid >= d) { xh += yh; xt += yt; }
        }
        if (tid < N_REL) {
            s_h[tid]   = h;
            s_off[tid] = xh - h;
            s_ti[tid]  = xt;
        }
    }
    __syncthreads();

    if (b >= s_ti[N_REL - 1]) return;
    int r = 0;
    while (b >= s_ti[r]) r++;
    int tiles_r  = (s_h[r] + TE - 1) / TE;
    int tile_idx = b - (s_ti[r] - tiles_r);
    int base     = s_off[r] + tile_idx * TE;
    int nE       = min(TE, s_off[r] + s_h[r] - base);

    uint32_t sA = smem_u32(sAB);
    uint32_t sB = sA + TE * 128;

    // stage B = permuted W_r^T bf16
    {
        const uint4* wsrc = (const uint4*)(g_Wbf + (size_t)r * IN_F * OUT_F);
        #pragma unroll
        for (int i = tid; i < 512; i += 128) {
            uint4 v = wsrc[i];
            sts128(sB + SW128((uint32_t)i * 16u), v.x, v.y, v.z, v.w);
        }
    }

    // COALESCED gather: 8 lanes per row x 16B; each row = ONE 128B line of g_nfb.
    // Lane cs==0 stages receiver, cs==1 stages inv (pair line shared by the 8 lanes).
    {
        int cs = lane & 7;        // 16B chunk within row
        int rs = lane >> 3;       // row within group of 4
        #pragma unroll
        for (int it = 0; it < 8; it++) {
            int row = it * 16 + w * 4 + rs;
            uint4 v = make_uint4(0u, 0u, 0u, 0u);
            if (row < nE) {
                int2 pr = g_pair[base + row];
                if (cs == 0) s_rc[row]  = pr.y;
                if (cs == 1) s_inv[row] = g_inv[pr.y];
                v = *((const uint4*)(g_nfb + (size_t)pr.x * IN_F) + cs);
            }
            sts128(sA + SW128((uint32_t)row * 128u + (uint32_t)cs * 16u), v.x, v.y, v.z, v.w);
        }
    }
    __syncthreads();

    float acc[2][8][4];
    #pragma unroll
    for (int mt = 0; mt < 2; mt++)
        #pragma unroll
        for (int j = 0; j < 8; j++)
            #pragma unroll
            for (int q = 0; q < 4; q++) acc[mt][j][q] = 0.f;

    mma_tile_pass(sA, sB, w, lane, acc);

    // Epilogue: permuted cols make thread tg's values logical [16tg,16tg+16);
    // scaled fp32 red.v2 straight into out (no agg buffer).
    int g  = lane >> 2;
    int tg = lane & 3;
    #pragma unroll
    for (int mt = 0; mt < 2; mt++) {
        int r1 = w * 32 + mt * 16 + g;
        int r2 = r1 + 8;
        if (r1 < nE) {
            float inv = s_inv[r1];
            float* p = out + (size_t)s_rc[r1] * OUT_F + 16 * tg;
            #pragma unroll
            for (int j = 0; j < 8; j++)
                red2f(p + 2 * j, acc[mt][j][0] * inv, acc[mt][j][1] * inv);
        }
        if (r2 < nE) {
            float inv = s_inv[r2];
            float* p = out + (size_t)s_rc[r2] * OUT_F + 16 * tg;
            #pragma unroll
            for (int j = 0; j < 8; j++)
                red2f(p + 2 * j, acc[mt][j][2] * inv, acc[mt][j][3] * inv);
        }
    }
}

// ---------------- launch ----------------
extern "C" void kernel_launch(void* const* d_in, const int* in_sizes, int n_in,
                              void* d_out, int out_size) {
    const float* node_features = (const float*)d_in[0];
    const int*   senders       = (const int*)d_in[1];
    const int*   receivers     = (const int*)d_in[2];
    const int*   rel_types     = (const int*)d_in[3];
    const float* basis         = (const float*)d_in[4];
    const float* coeff         = (const float*)d_in[5];
    const float* self_weight   = (const float*)d_in[6];
    const float* bias          = (const float*)d_in[7];
    float* out = (float*)d_out;

    int N = in_sizes[0] / IN_F;
    int E = in_sizes[1];
    if (N > MAX_NODES) N = MAX_NODES;
    if (E > MAX_EDGES) E = MAX_EDGES;

    setup_k<<<ZERO_BLOCKS + NFB_BLOCKS + N_REL + 1, 256>>>(
        basis, coeff, self_weight, node_features, N);
    hist_deg_k<<<512, 256>>>(rel_types, receivers, E);
    scatter_k<<<512, 256>>>(rel_types, senders, receivers, E);
    self_hmma_k<<<(N + TE - 1) / TE, 128>>>(node_features, bias, out, N);

    int max_tiles = (E + TE - 1) / TE + N_REL;
    edge_mma_k<<<max_tiles, 128>>>(out);
}

// round 15
// speedup vs baseline: 1.5782x; 1.5782x over previous
#include <cuda_runtime.h>
#include <cuda_bf16.h>
#include <cstdint>

#define N_REL   32
#define N_BASES 30
#define IN_F    64
#define OUT_F   64
#define MAX_NODES 100000
#define MAX_EDGES 1000000
#define TE      128   // rows per tile

// ---------------- device scratch (static, allocation-free) ----------------
__device__ __nv_bfloat16  g_Wbf[N_REL * OUT_F * IN_F];   // bf16 W^T per relation, ROW-PERMUTED
__device__ __nv_bfloat16  g_SWhi[OUT_F * IN_F];          // self_weight^T hi, ROW-PERMUTED
__device__ __nv_bfloat16  g_SWlo[OUT_F * IN_F];          // self_weight^T lo, ROW-PERMUTED
__device__ __nv_bfloat16  g_agg[MAX_NODES * OUT_F];      // bf16 edge-message accumulator (logical cols)
__device__ __nv_bfloat16  g_nfb[MAX_NODES * IN_F];       // bf16 node features (128B rows)
__device__ float g_deg[MAX_NODES];
__device__ int   g_cnt[N_REL];                           // per-relation edge counts (atomic cursor)
__device__ int2  g_pair[(size_t)N_REL * MAX_EDGES];      // per-relation slabs: (sender, receiver)

// Permutation: logical output col o lives at physical B-row p(o).
// o = 16*tg + 2*j + b  ->  p = 8*j + 2*tg + b
__host__ __device__ __forceinline__ int permcol(int o) {
    return 8 * ((o >> 1) & 7) + 2 * (o >> 4) + (o & 1);
}

// ---------------- helpers ----------------
__device__ __forceinline__ uint32_t smem_u32(const void* p) {
    uint32_t a;
    asm("{ .reg .u64 t; cvta.to.shared.u64 t, %1; cvt.u32.u64 %0, t; }" : "=r"(a) : "l"(p));
    return a;
}
__device__ __forceinline__ uint32_t bf2pack(float lo, float hi) {
    uint32_t r;
    asm("cvt.rn.bf16x2.f32 %0, %1, %2;" : "=r"(r) : "f"(hi), "f"(lo));
    return r;
}
// hi/lo split of two floats into packed bf16x2 (keeps live registers minimal)
__device__ __forceinline__ void split2(float x, float y, uint32_t& h, uint32_t& l) {
    uint32_t hp = bf2pack(x, y);
    __nv_bfloat162 hb = *(__nv_bfloat162*)&hp;
    l = bf2pack(x - __low2float(hb), y - __high2float(hb));
    h = hp;
}
__device__ __forceinline__ void sts128(uint32_t addr, uint32_t a, uint32_t b, uint32_t c, uint32_t d) {
    asm volatile("st.shared.v4.b32 [%0], {%1, %2, %3, %4};" :: "r"(addr), "r"(a), "r"(b), "r"(c), "r"(d) : "memory");
}
__device__ __forceinline__ void red_v2_bf16x2(__nv_bfloat16* p, uint32_t a, uint32_t b) {
    asm volatile("red.global.add.noftz.v2.bf16x2 [%0], {%1, %2};"
                 :: "l"(p), "r"(a), "r"(b) : "memory");
}
__device__ __forceinline__ void ldm_x4(uint32_t& r0, uint32_t& r1, uint32_t& r2, uint32_t& r3,
                                       uint32_t addr) {
    asm volatile("ldmatrix.sync.aligned.m8n8.x4.shared.b16 {%0, %1, %2, %3}, [%4];"
                 : "=r"(r0), "=r"(r1), "=r"(r2), "=r"(r3) : "r"(addr));
}
__device__ __forceinline__ void mma_bf16(float* d, uint32_t a0, uint32_t a1, uint32_t a2,
                                         uint32_t a3, uint32_t b0, uint32_t b1) {
    asm volatile("mma.sync.aligned.m16n8k16.row.col.f32.bf16.bf16.f32 "
                 "{%0, %1, %2, %3}, {%4, %5, %6, %7}, {%8, %9}, {%0, %1, %2, %3};"
                 : "+f"(d[0]), "+f"(d[1]), "+f"(d[2]), "+f"(d[3])
                 : "r"(a0), "r"(a1), "r"(a2), "r"(a3), "r"(b0), "r"(b1));
}

#define SW128(o) ((o) ^ (((o) >> 3) & 0x70))
#define ZERO_BLOCKS ((MAX_NODES + 255) / 256)
#define AGG_BLOCKS  ((MAX_NODES * 8 + 255) / 256)   // uint4 = 8 bf16 per thread
#define NFB_BLOCKS  ((MAX_NODES * 8 + 255) / 256)

// One MMA pass over a 128x64 @ 64x64 tile pair; accumulates into acc.
__device__ __forceinline__ void mma_tile_pass(uint32_t sA, uint32_t sB, int w, int lane,
                                              float (&acc)[2][8][4]) {
    #pragma unroll
    for (int k = 0; k < 4; k++) {
        uint32_t a[2][4];
        #pragma unroll
        for (int mt = 0; mt < 2; mt++) {
            uint32_t row = (uint32_t)(w * 32 + mt * 16 + (((lane >> 3) & 1) << 3) + (lane & 7));
            uint32_t kb  = (uint32_t)(32 * k + (((lane >> 4) & 1) << 4));
            ldm_x4(a[mt][0], a[mt][1], a[mt][2], a[mt][3], sA + SW128(row * 128u + kb));
        }
        uint32_t bf[8][2];
        #pragma unroll
        for (int jp = 0; jp < 4; jp++) {
            uint32_t jl   = (uint32_t)((lane >> 4) & 1);
            uint32_t half = (uint32_t)((lane >> 3) & 1);
            uint32_t rowb = (uint32_t)(8 * (2 * jp + jl) + (lane & 7));
            uint32_t kb   = (uint32_t)(32 * k + 16 * half);
            ldm_x4(bf[2 * jp][0], bf[2 * jp][1], bf[2 * jp + 1][0], bf[2 * jp + 1][1],
                   sB + SW128(rowb * 128u + kb));
        }
        #pragma unroll
        for (int mt = 0; mt < 2; mt++)
            #pragma unroll
            for (int j = 0; j < 8; j++)
                mma_bf16(acc[mt][j], a[mt][0], a[mt][1], a[mt][2], a[mt][3],
                         bf[j][0], bf[j][1]);
    }
}

// ---------------- setup: zero deg/cnt/agg + nf->bf16 + permuted W_r + permuted SW hi/lo ----------------
__global__ void setup_k(const float* __restrict__ basis, const float* __restrict__ coeff,
                        const float* __restrict__ sw, const float* __restrict__ nf, int N) {
    int b = blockIdx.x;
    if (b < ZERO_BLOCKS) {
        int i = b * 256 + threadIdx.x;
        if (i < N) g_deg[i] = 0.f;
        if (b == 0 && threadIdx.x < N_REL) g_cnt[threadIdx.x] = 0;
        return;
    }
    if (b < ZERO_BLOCKS + AGG_BLOCKS) {
        int i = (b - ZERO_BLOCKS) * 256 + threadIdx.x;
        if (i < N * 8)
            ((uint4*)g_agg)[i] = make_uint4(0u, 0u, 0u, 0u);
        return;
    }
    if (b < ZERO_BLOCKS + AGG_BLOCKS + NFB_BLOCKS) {
        int i = (b - ZERO_BLOCKS - AGG_BLOCKS) * 256 + threadIdx.x;
        if (i < N * 8) {
            const float4* src = (const float4*)nf + 2 * (size_t)i;
            float4 f0 = src[0];
            float4 f1 = src[1];
            ((uint4*)g_nfb)[i] = make_uint4(bf2pack(f0.x, f0.y), bf2pack(f0.z, f0.w),
                                            bf2pack(f1.x, f1.y), bf2pack(f1.z, f1.w));
        }
        return;
    }
    if (b == ZERO_BLOCKS + AGG_BLOCKS + NFB_BLOCKS + N_REL) {
        for (int idx = threadIdx.x; idx < IN_F * OUT_F; idx += blockDim.x) {
            int i = idx / OUT_F, o = idx % OUT_F;
            float x = sw[idx];
            uint32_t hp, lp;
            split2(x, 0.f, hp, lp);
            int p = permcol(o);
            g_SWhi[p * IN_F + i] = *(__nv_bfloat16*)&hp;
            g_SWlo[p * IN_F + i] = *(__nv_bfloat16*)&lp;
        }
        return;
    }
    int r = b - ZERO_BLOCKS - AGG_BLOCKS - NFB_BLOCKS;  // 0..N_REL-1
    __shared__ float c[N_BASES];
    if (threadIdx.x < N_BASES) c[threadIdx.x] = coeff[r * N_BASES + threadIdx.x];
    __syncthreads();
    for (int idx = threadIdx.x; idx < IN_F * OUT_F; idx += blockDim.x) {
        float acc = 0.f;
        #pragma unroll
        for (int bb = 0; bb < N_BASES; bb++)
            acc += c[bb] * basis[bb * IN_F * OUT_F + idx];
        int i = idx / OUT_F, o = idx % OUT_F;
        g_Wbf[r * IN_F * OUT_F + permcol(o) * IN_F + i] = __float2bfloat16(acc);
    }
}

// ---------------- fused deg + counting-sort (ONE pass; per-relation private slabs) ----------------
// No global prefix needed: relation r's slab starts at r*MAX_EDGES; blocks reserve
// contiguous ranges inside the slab with a single atomicAdd on g_cnt[r].
__global__ void sort_deg_k(const int* __restrict__ rel,
                           const int* __restrict__ senders,
                           const int* __restrict__ receivers, int E) {
    __shared__ int cnt[N_REL];
    __shared__ int basee[N_REL];
    int tid = threadIdx.x;
    if (tid < N_REL) cnt[tid] = 0;
    __syncthreads();

    int chunk = (E + gridDim.x - 1) / gridDim.x;
    int s = blockIdx.x * chunk;
    int e_end = min(E, s + chunk);
    for (int i = s + tid; i < e_end; i += blockDim.x) {
        atomicAdd(&cnt[rel[i]], 1);
        atomicAdd(&g_deg[receivers[i]], 1.f);
    }
    __syncthreads();
    if (tid < N_REL)
        basee[tid] = atomicAdd(&g_cnt[tid], cnt[tid]);
    __syncthreads();
    if (tid < N_REL) cnt[tid] = 0;
    __syncthreads();
    for (int i = s + tid; i < e_end; i += blockDim.x) {
        int r = rel[i];
        int p = atomicAdd(&cnt[r], 1);
        g_pair[(size_t)r * MAX_EDGES + basee[r] + p] = make_int2(senders[i], receivers[i]);
    }
}

// ---------------- edge messages: coalesced bf16 gather -> HMMA -> red.v2.bf16x2 (R12-proven) ----------------
__global__ void __launch_bounds__(128, 4)
edge_mma_k() {
    __shared__ __align__(128) uint8_t sAB[TE * 128 + OUT_F * 128];  // A:16KB, B:8KB
    __shared__ int   s_snd[TE];
    __shared__ int   s_rc[TE];
    __shared__ int   s_h[N_REL];
    __shared__ int   s_ti[N_REL];

    int tid  = threadIdx.x;
    int w    = tid >> 5;
    int lane = tid & 31;
    int b    = blockIdx.x;

    // 32-wide scan of per-relation TILE counts (edge offsets not needed: private slabs)
    if (tid < 32) {
        int h = (tid < N_REL) ? g_cnt[tid] : 0;
        int t = (h + TE - 1) / TE;
        int xt = t;
        #pragma unroll
        for (int d = 1; d < 32; d <<= 1) {
            int yt = __shfl_up_sync(0xffffffffu, xt, d);
            if (tid >= d) xt += yt;
        }
        if (tid < N_REL) {
            s_h[tid]  = h;
            s_ti[tid] = xt;   // inclusive tile prefix
        }
    }
    __syncthreads();

    if (b >= s_ti[N_REL - 1]) return;
    int r = 0;
    while (b >= s_ti[r]) r++;
    int tiles_r  = (s_h[r] + TE - 1) / TE;
    int tile_idx = b - (s_ti[r] - tiles_r);
    int base_in  = tile_idx * TE;                    // offset within relation slab
    int nE       = min(TE, s_h[r] - base_in);
    const int2* pair_base = g_pair + (size_t)r * MAX_EDGES + base_in;

    uint32_t sA = smem_u32(sAB);
    uint32_t sB = sA + TE * 128;

    // stage B = permuted W_r^T bf16
    {
        const uint4* wsrc = (const uint4*)(g_Wbf + (size_t)r * IN_F * OUT_F);
        #pragma unroll
        for (int i = tid; i < 512; i += 128) {
            uint4 v = wsrc[i];
            sts128(sB + SW128((uint32_t)i * 16u), v.x, v.y, v.z, v.w);
        }
    }

    // stage (sender, receiver) for this tile
    if (tid < nE) {
        int2 pr = pair_base[tid];
        s_snd[tid] = pr.x;
        s_rc[tid]  = pr.y;
    }
    __syncthreads();

    // COALESCED gather: 8 lanes per row x 16B; each row = ONE 128B line of g_nfb.
    {
        int cs = lane & 7;
        int rs = lane >> 3;
        #pragma unroll
        for (int it = 0; it < 8; it++) {
            int row = it * 16 + w * 4 + rs;
            uint4 v = make_uint4(0u, 0u, 0u, 0u);
            if (row < nE)
                v = *((const uint4*)(g_nfb + (size_t)s_snd[row] * IN_F) + cs);
            sts128(sA + SW128((uint32_t)row * 128u + (uint32_t)cs * 16u), v.x, v.y, v.z, v.w);
        }
    }
    __syncthreads();

    float acc[2][8][4];
    #pragma unroll
    for (int mt = 0; mt < 2; mt++)
        #pragma unroll
        for (int j = 0; j < 8; j++)
            #pragma unroll
            for (int q = 0; q < 4; q++) acc[mt][j][q] = 0.f;

    mma_tile_pass(sA, sB, w, lane, acc);

    // Epilogue: permuted cols -> thread tg owns logical [16tg,16tg+16);
    // 8B red.v2.bf16x2 covering 4 cols, 16 REDG/thread (R12-proven).
    int g  = lane >> 2;
    int tg = lane & 3;
    #pragma unroll
    for (int mt = 0; mt < 2; mt++) {
        int r1 = w * 32 + mt * 16 + g;
        int r2 = r1 + 8;
        if (r1 < nE) {
            __nv_bfloat16* p = g_agg + (size_t)s_rc[r1] * OUT_F + 16 * tg;
            #pragma unroll
            for (int q = 0; q < 4; q++)
                red_v2_bf16x2(p + 4 * q,
                              bf2pack(acc[mt][2 * q][0],     acc[mt][2 * q][1]),
                              bf2pack(acc[mt][2 * q + 1][0], acc[mt][2 * q + 1][1]));
        }
        if (r2 < nE) {
            __nv_bfloat16* p = g_agg + (size_t)s_rc[r2] * OUT_F + 16 * tg;
            #pragma unroll
            for (int q = 0; q < 4; q++)
                red_v2_bf16x2(p + 4 * q,
                              bf2pack(acc[mt][2 * q][2],     acc[mt][2 * q][3]),
                              bf2pack(acc[mt][2 * q + 1][2], acc[mt][2 * q + 1][3]));
        }
    }
}

// ---------------- self term (bf16-split HMMA) + final merge: out = X@SW + bias + inv*agg ----------------
__global__ void __launch_bounds__(128) self_hmma_k(const float* __restrict__ nf,
                                                   const float* __restrict__ bias,
                                                   float* __restrict__ out, int N) {
    __shared__ __align__(128) uint8_t sm[TE * 128 * 2 + OUT_F * 128 * 2];  // Ah,Al,Bh,Bl = 48KB
    int tid  = threadIdx.x;
    int w    = tid >> 5;
    int lane = tid & 31;
    int base = blockIdx.x * TE;
    int nR   = min(TE, N - base);

    uint32_t sAh = smem_u32(sm);
    uint32_t sAl = sAh + TE * 128;
    uint32_t sBh = sAl + TE * 128;
    uint32_t sBl = sBh + OUT_F * 128;

    // stage B hi/lo (already permuted in setup)
    {
        const uint4* bh = (const uint4*)g_SWhi;
        const uint4* bl = (const uint4*)g_SWlo;
        #pragma unroll
        for (int i = tid; i < 512; i += 128) {
            uint32_t off = SW128((uint32_t)i * 16u);
            uint4 vh = bh[i];
            uint4 vl = bl[i];
            sts128(sBh + off, vh.x, vh.y, vh.z, vh.w);
            sts128(sBl + off, vl.x, vl.y, vl.z, vl.w);
        }
    }

    // load + split A row `tid` — 8 floats per step keeps live registers minimal
    {
        uint32_t rowbase = (uint32_t)tid * 128u;
        if (tid < nR) {
            const float4* src = (const float4*)(nf + (size_t)(base + tid) * IN_F);
            #pragma unroll
            for (int c = 0; c < 8; c++) {
                float4 f0 = src[2 * c];
                float4 f1 = src[2 * c + 1];
                uint32_t h0, h1, h2, h3, l0, l1, l2, l3;
                split2(f0.x, f0.y, h0, l0);
                split2(f0.z, f0.w, h1, l1);
                split2(f1.x, f1.y, h2, l2);
                split2(f1.z, f1.w, h3, l3);
                uint32_t off = SW128(rowbase + (uint32_t)c * 16u);
                sts128(sAh + off, h0, h1, h2, h3);
                sts128(sAl + off, l0, l1, l2, l3);
            }
        } else {
            #pragma unroll
            for (int c = 0; c < 8; c++) {
                uint32_t off = SW128(rowbase + (uint32_t)c * 16u);
                sts128(sAh + off, 0u, 0u, 0u, 0u);
                sts128(sAl + off, 0u, 0u, 0u, 0u);
            }
        }
    }
    __syncthreads();

    float acc[2][8][4];
    #pragma unroll
    for (int mt = 0; mt < 2; mt++)
        #pragma unroll
        for (int j = 0; j < 8; j++)
            #pragma unroll
            for (int q = 0; q < 4; q++) acc[mt][j][q] = 0.f;

    mma_tile_pass(sAh, sBh, w, lane, acc);
    mma_tile_pass(sAh, sBl, w, lane, acc);
    mma_tile_pass(sAl, sBh, w, lane, acc);

    // epilogue: thread owns logical cols [16tg, 16tg+16) -> float4 stores.
    // out = acc + bias + inv_deg * agg
    int g  = lane >> 2;
    int tg = lane & 3;
    float4 bv[4];
    #pragma unroll
    for (int q = 0; q < 4; q++) bv[q] = *(const float4*)&bias[16 * tg + 4 * q];
    #pragma unroll
    for (int mt = 0; mt < 2; mt++) {
        int r1 = base + w * 32 + mt * 16 + g;
        int r2 = r1 + 8;
        float inv1 = 0.f, inv2 = 0.f;
        if (r1 < N) inv1 = 1.f / fmaxf(g_deg[r1], 1.f);
        if (r2 < N) inv2 = 1.f / fmaxf(g_deg[r2], 1.f);
        #pragma unroll
        for (int q = 0; q < 4; q++) {
            if (r1 < N) {
                uint2 u = *(const uint2*)(g_agg + (size_t)r1 * OUT_F + 16 * tg + 4 * q);
                __nv_bfloat162 a0 = *(__nv_bfloat162*)&u.x;
                __nv_bfloat162 a1 = *(__nv_bfloat162*)&u.y;
                *(float4*)(out + (size_t)r1 * OUT_F + 16 * tg + 4 * q) = make_float4(
                    acc[mt][2 * q][0]     + bv[q].x + inv1 * __low2float(a0),
                    acc[mt][2 * q][1]     + bv[q].y + inv1 * __high2float(a0),
                    acc[mt][2 * q + 1][0] + bv[q].z + inv1 * __low2float(a1),
                    acc[mt][2 * q + 1][1] + bv[q].w + inv1 * __high2float(a1));
            }
            if (r2 < N) {
                uint2 u = *(const uint2*)(g_agg + (size_t)r2 * OUT_F + 16 * tg + 4 * q);
                __nv_bfloat162 a0 = *(__nv_bfloat162*)&u.x;
                __nv_bfloat162 a1 = *(__nv_bfloat162*)&u.y;
                *(float4*)(out + (size_t)r2 * OUT_F + 16 * tg + 4 * q) = make_float4(
                    acc[mt][2 * q][2]     + bv[q].x + inv2 * __low2float(a0),
                    acc[mt][2 * q][3]     + bv[q].y + inv2 * __high2float(a0),
                    acc[mt][2 * q + 1][2] + bv[q].z + inv2 * __low2float(a1),
                    acc[mt][2 * q + 1][3] + bv[q].w + inv2 * __high2float(a1));
            }
        }
    }
}

// ---------------- launch ----------------
extern "C" void kernel_launch(void* const* d_in, const int* in_sizes, int n_in,
                              void* d_out, int out_size) {
    const float* node_features = (const float*)d_in[0];
    const int*   senders       = (const int*)d_in[1];
    const int*   receivers     = (const int*)d_in[2];
    const int*   rel_types     = (const int*)d_in[3];
    const float* basis         = (const float*)d_in[4];
    const float* coeff         = (const float*)d_in[5];
    const float* self_weight   = (const float*)d_in[6];
    const float* bias          = (const float*)d_in[7];
    float* out = (float*)d_out;

    int N = in_sizes[0] / IN_F;
    int E = in_sizes[1];
    if (N > MAX_NODES) N = MAX_NODES;
    if (E > MAX_EDGES) E = MAX_EDGES;

    setup_k<<<ZERO_BLOCKS + AGG_BLOCKS + NFB_BLOCKS + N_REL + 1, 256>>>(
        basis, coeff, self_weight, node_features, N);
    sort_deg_k<<<512, 256>>>(rel_types, senders, receivers, E);

    int max_tiles = (E + TE - 1) / TE + N_REL;
    edge_mma_k<<<max_tiles, 128>>>();
    self_hmma_k<<<(N + TE - 1) / TE, 128>>>(node_features, bias, out, N);
}